// round 4
// baseline (speedup 1.0000x reference)
#include <cuda_runtime.h>
#include <cuda_bf16.h>
#include <cstddef>

// Depthwise cross-correlation:
//   out[ch, oy, ox] = sum_{ky,kx} x[ch, oy+ky, ox+kx] * z[ch, ky, kx]
//   ch in [0, 128*256), x: 31x31, z: 7x7, out: 25x25 (VALID, no flip)

#define NCHAN   (128 * 256)
#define HX      31
#define HZ      7
#define HO      25
#define XSZ     (HX * HX)   // 961
#define ZSZ     (HZ * HZ)   // 49
#define OSZ     (HO * HO)   // 625
#define CPB     5           // channels per block
#define TPC     25          // threads per channel (one per output column)
#define THREADS 128
// Channel pitch in SMEM: 985 mod 32 == 25 -> x loads are bank-conflict-free
// for the (lch, tx) lane layout across all 4 warps (verified per-warp).
#define XPITCH  985

__global__ __launch_bounds__(THREADS)
void dwxcorr_kernel(const float* __restrict__ z,
                    const float* __restrict__ x,
                    float* __restrict__ out) {
    __shared__ float sx[CPB * XPITCH];   // 19700 B
    __shared__ float sk[CPB * ZSZ];      //   980 B

    const int tid    = threadIdx.x;
    const int chBase = blockIdx.x * CPB;

    // ---- Cooperative staging: 5 channels of x are contiguous in gmem ----
    #pragma unroll
    for (int lc = 0; lc < CPB; ++lc) {
        const int ch = chBase + lc;
        if (ch < NCHAN) {
            const float* gx = x + (size_t)ch * XSZ;
            for (int i = tid; i < XSZ; i += THREADS)
                sx[lc * XPITCH + i] = gx[i];
            if (tid < ZSZ)
                sk[lc * ZSZ + tid] = z[(size_t)ch * ZSZ + tid];
        }
    }
    __syncthreads();

    const int lch = tid / TPC;           // local channel 0..4 (5 = idle lanes)
    const int tx  = tid - lch * TPC;     // output column 0..24
    const int ch  = chBase + lch;
    if (lch >= CPB || ch >= NCHAN) return;

    // Kernel taps: one-time broadcast LDS into registers.
    float kk[ZSZ];
    #pragma unroll
    for (int j = 0; j < ZSZ; ++j) kk[j] = sk[lch * ZSZ + j];

    float acc[HO];
    #pragma unroll
    for (int i = 0; i < HO; ++i) acc[i] = 0.0f;

    // Each x element in this thread's 7-wide column window is loaded exactly
    // once; fully unrolled so acc[oy] indices are compile-time constants.
    const float* xb = &sx[lch * XPITCH + tx];
    #pragma unroll
    for (int r = 0; r < HX; ++r) {
        float xr[HZ];
        #pragma unroll
        for (int c = 0; c < HZ; ++c)
            xr[c] = xb[r * HX + c];
        #pragma unroll
        for (int ky = 0; ky < HZ; ++ky) {
            const int oy = r - ky;
            if (oy >= 0 && oy < HO) {
                #pragma unroll
                for (int kx = 0; kx < HZ; ++kx)
                    acc[oy] = fmaf(xr[kx], kk[ky * HZ + kx], acc[oy]);
            }
        }
    }

    float* go = out + (size_t)ch * OSZ + tx;
    #pragma unroll
    for (int oy = 0; oy < HO; ++oy)
        go[oy * HO] = acc[oy];
}

extern "C" void kernel_launch(void* const* d_in, const int* in_sizes, int n_in,
                              void* d_out, int out_size) {
    // metadata order: d_in[0] = z_f [128,256,7,7], d_in[1] = x_f [128,256,31,31]
    const float* z = (const float*)d_in[0];
    const float* x = (const float*)d_in[1];
    float* out = (float*)d_out;

    const int grid = (NCHAN + CPB - 1) / CPB;   // 6554
    dwxcorr_kernel<<<grid, THREADS>>>(z, x, out);
}

// round 5
// speedup vs baseline: 1.0924x; 1.0924x over previous
#include <cuda_runtime.h>
#include <cuda_bf16.h>
#include <cstddef>

// Depthwise cross-correlation:
//   out[ch, oy, ox] = sum_{ky,kx} x[ch, oy+ky, ox+kx] * z[ch, ky, kx]
//   ch in [0, 128*256), x: 31x31, z: 7x7, out: 25x25 (VALID, no flip)
//
// R4 change vs R3: ring accumulator (7 live accs instead of 25) to kill the
// register spills diagnosed from fma=24%/issue=38%/L1=33% in the R3 profile.

#define NCHAN   (128 * 256)
#define HX      31
#define HZ      7
#define HO      25
#define XSZ     (HX * HX)   // 961
#define ZSZ     (HZ * HZ)   // 49
#define OSZ     (HO * HO)   // 625
#define CPB     5           // channels per block
#define TPC     25          // threads per channel (one per output column)
#define THREADS 128
// Channel pitch in SMEM: 985 mod 32 == 25 -> the (lch, tx) lane layout hits
// all 32 banks exactly once per warp on every x row load (conflict-free).
#define XPITCH  985

__global__ __launch_bounds__(THREADS, 6)
void dwxcorr_kernel(const float* __restrict__ z,
                    const float* __restrict__ x,
                    float* __restrict__ out) {
    __shared__ float sx[CPB * XPITCH];   // 19700 B
    __shared__ float sk[CPB * ZSZ];      //   980 B

    const int tid    = threadIdx.x;
    const int chBase = blockIdx.x * CPB;

    // ---- Cooperative staging: 5 channels of x are contiguous in gmem ----
    #pragma unroll
    for (int lc = 0; lc < CPB; ++lc) {
        const int ch = chBase + lc;
        if (ch < NCHAN) {
            const float* gx = x + (size_t)ch * XSZ;
            for (int i = tid; i < XSZ; i += THREADS)
                sx[lc * XPITCH + i] = gx[i];
            if (tid < ZSZ)
                sk[lc * ZSZ + tid] = z[(size_t)ch * ZSZ + tid];
        }
    }
    __syncthreads();

    const int lch = tid / TPC;           // local channel 0..4 (5 = idle lanes)
    const int tx  = tid - lch * TPC;     // output column 0..24
    const int ch  = chBase + lch;
    if (lch >= CPB || ch >= NCHAN) return;

    // Kernel taps: one-time broadcast LDS into registers (49 floats).
    float kk[ZSZ];
    #pragma unroll
    for (int j = 0; j < ZSZ; ++j) kk[j] = sk[lch * ZSZ + j];

    // Ring of 7 accumulators: at x-row r, output rows [r-6, r] are live.
    float acc[HZ];
    #pragma unroll
    for (int i = 0; i < HZ; ++i) acc[i] = 0.0f;

    const float* xb = &sx[lch * XPITCH + tx];
    float*       go = out + (size_t)ch * OSZ + tx;

    #pragma unroll
    for (int r = 0; r < HX; ++r) {
        float xr[HZ];
        #pragma unroll
        for (int c = 0; c < HZ; ++c)
            xr[c] = xb[r * HX + c];

        #pragma unroll
        for (int ky = 0; ky < HZ; ++ky) {
            const int oy = r - ky;
            if (oy >= 0 && oy < HO) {
                const int slot = oy % HZ;          // compile-time after unroll
                #pragma unroll
                for (int kx = 0; kx < HZ; ++kx)
                    acc[slot] = fmaf(xr[kx], kk[ky * HZ + kx], acc[slot]);
            }
        }

        // Output row r-6 is complete: store it and recycle the slot.
        if (r >= HZ - 1) {
            const int oy   = r - (HZ - 1);
            const int slot = oy % HZ;
            go[oy * HO] = acc[slot];
            acc[slot] = 0.0f;
        }
    }
}

extern "C" void kernel_launch(void* const* d_in, const int* in_sizes, int n_in,
                              void* d_out, int out_size) {
    // metadata order: d_in[0] = z_f [128,256,7,7], d_in[1] = x_f [128,256,31,31]
    const float* z = (const float*)d_in[0];
    const float* x = (const float*)d_in[1];
    float* out = (float*)d_out;

    const int grid = (NCHAN + CPB - 1) / CPB;   // 6554
    dwxcorr_kernel<<<grid, THREADS>>>(z, x, out);
}